// round 11
// baseline (speedup 1.0000x reference)
#include <cuda_runtime.h>
#include <cstdint>

// out[b,t,a] = start_state[b,a] + (t/255) * patterns[iid[b], t, a]
// B=256, T=256, AD=64 -> each (b,t) row = 64 floats = 8 x 256-bit vectors.
//
// R11: v8 x 8. One CTA per batch row (256 CTAs x 256 threads); each thread
// does 8 front-batched 256-bit loads + 8 stores (256B in flight/thread).
// Lowest dynamic-instruction-count per output byte in the series:
// iid/start_state/base addressing amortized over 8 items.

#define B_   256
#define T_   256
#define AD_  64
#define TPB  256
#define ITEMS 8                 // v8 items per thread (t stride 32)

struct f8 { float v[8]; };

__device__ __forceinline__ f8 ldg_v8(const float* p) {
    f8 r;
    asm volatile("ld.global.nc.v8.f32 {%0,%1,%2,%3,%4,%5,%6,%7}, [%8];"
                 : "=f"(r.v[0]), "=f"(r.v[1]), "=f"(r.v[2]), "=f"(r.v[3]),
                   "=f"(r.v[4]), "=f"(r.v[5]), "=f"(r.v[6]), "=f"(r.v[7])
                 : "l"(p));
    return r;
}

__device__ __forceinline__ void stg_v8(float* p, const f8& r) {
    asm volatile("st.global.v8.f32 [%0], {%1,%2,%3,%4,%5,%6,%7,%8};"
                 :: "l"(p),
                    "f"(r.v[0]), "f"(r.v[1]), "f"(r.v[2]), "f"(r.v[3]),
                    "f"(r.v[4]), "f"(r.v[5]), "f"(r.v[6]), "f"(r.v[7])
                 : "memory");
}

__global__ __launch_bounds__(TPB)
void traj_kernel(const float* __restrict__ start_state,    // [B, 64]
                 const int*   __restrict__ instruction_id, // [B]
                 const float* __restrict__ patterns,       // [V, T, 64]
                 float*       __restrict__ out)            // [B, T, 64]
{
    const unsigned b    = blockIdx.x;          // one CTA per batch row
    const unsigned tid  = threadIdx.x;
    const unsigned a8   = tid & 7u;            // 256-bit slot within 64-float row
    const unsigned trow = tid >> 3;            // 0..31

    const int iid = __ldg(&instruction_id[b]);

    const f8 s = ldg_v8(start_state + (size_t)b * AD_ + a8 * 8u);

    const float* __restrict__ pat =
        patterns + (size_t)iid * T_ * AD_ + a8 * 8u;
    float* __restrict__ dst =
        out + (size_t)b * T_ * AD_ + a8 * 8u;

    // 8 independent 256-bit loads, front-batched (t stride 32).
    f8 p[ITEMS];
#pragma unroll
    for (int i = 0; i < ITEMS; i++)
        p[i] = ldg_v8(pat + (size_t)(trow + i * 32u) * AD_);

#pragma unroll
    for (int i = 0; i < ITEMS; i++) {
        const unsigned t = trow + (unsigned)i * 32u;
        const float prog = (float)t * (1.0f / (float)(T_ - 1));
        f8 r;
#pragma unroll
        for (int k = 0; k < 8; k++) r.v[k] = fmaf(prog, p[i].v[k], s.v[k]);
        stg_v8(dst + (size_t)t * AD_, r);
    }
}

extern "C" void kernel_launch(void* const* d_in, const int* in_sizes, int n_in,
                              void* d_out, int out_size)
{
    const float* start_state    = (const float*)d_in[0];
    const int*   instruction_id = (const int*)  d_in[1];
    const float* patterns       = (const float*)d_in[27];
    float*       out            = (float*)d_out;

    traj_kernel<<<B_, TPB>>>(start_state, instruction_id, patterns, out);
}

// round 12
// speedup vs baseline: 1.0323x; 1.0323x over previous
#include <cuda_runtime.h>
#include <cstdint>

// out[b,t,a] = start_state[b,a] + (t/255) * patterns[iid[b], t, a]
// B=256, T=256, AD=64 -> each (b,t) row = 64 floats = 8 x 256-bit vectors.
//
// R12: hybrid of the two best kernels.
//   - R10's per-thread width: 4 front-batched 256-bit loads + 4 stores
//   - R9's coverage: 1024 CTAs (TPB=128, quarter-row per CTA)
// 1 warp/SMSP/CTA, ~7 CTAs/SM of independent load batches.

#define B_   256
#define T_   256
#define AD_  64
#define TPB  128
#define ITEMS 4                 // v8 items per thread (t stride 16 within chunk)
#define CHUNKS_PER_B 4          // 256 t / (16 trows * 4 items)

struct f8 { float v[8]; };

__device__ __forceinline__ f8 ldg_v8(const float* p) {
    f8 r;
    asm volatile("ld.global.nc.v8.f32 {%0,%1,%2,%3,%4,%5,%6,%7}, [%8];"
                 : "=f"(r.v[0]), "=f"(r.v[1]), "=f"(r.v[2]), "=f"(r.v[3]),
                   "=f"(r.v[4]), "=f"(r.v[5]), "=f"(r.v[6]), "=f"(r.v[7])
                 : "l"(p));
    return r;
}

__device__ __forceinline__ void stg_v8(float* p, const f8& r) {
    asm volatile("st.global.v8.f32 [%0], {%1,%2,%3,%4,%5,%6,%7,%8};"
                 :: "l"(p),
                    "f"(r.v[0]), "f"(r.v[1]), "f"(r.v[2]), "f"(r.v[3]),
                    "f"(r.v[4]), "f"(r.v[5]), "f"(r.v[6]), "f"(r.v[7])
                 : "memory");
}

__global__ __launch_bounds__(TPB)
void traj_kernel(const float* __restrict__ start_state,    // [B, 64]
                 const int*   __restrict__ instruction_id, // [B]
                 const float* __restrict__ patterns,       // [V, T, 64]
                 float*       __restrict__ out)            // [B, T, 64]
{
    const unsigned bid   = blockIdx.x;
    const unsigned b     = bid >> 2;           // 4 chunks of 64 t per batch row
    const unsigned chunk = bid & 3u;
    const unsigned tid   = threadIdx.x;
    const unsigned a8    = tid & 7u;           // 256-bit slot within 64-float row
    const unsigned trow  = tid >> 3;           // 0..15
    const unsigned tbase = chunk * 64u;        // chunk covers 64 t values

    const int iid = __ldg(&instruction_id[b]);

    const f8 s = ldg_v8(start_state + (size_t)b * AD_ + a8 * 8u);

    const float* __restrict__ pat =
        patterns + ((size_t)iid * T_ + tbase) * AD_ + a8 * 8u;
    float* __restrict__ dst =
        out + ((size_t)b * T_ + tbase) * AD_ + a8 * 8u;

    // 4 independent 256-bit loads, front-batched (t stride 16 within chunk).
    f8 p[ITEMS];
#pragma unroll
    for (int i = 0; i < ITEMS; i++)
        p[i] = ldg_v8(pat + (size_t)(trow + i * 16u) * AD_);

#pragma unroll
    for (int i = 0; i < ITEMS; i++) {
        const unsigned tl = trow + (unsigned)i * 16u;
        const float prog = (float)(tbase + tl) * (1.0f / (float)(T_ - 1));
        f8 r;
#pragma unroll
        for (int k = 0; k < 8; k++) r.v[k] = fmaf(prog, p[i].v[k], s.v[k]);
        stg_v8(dst + (size_t)tl * AD_, r);
    }
}

extern "C" void kernel_launch(void* const* d_in, const int* in_sizes, int n_in,
                              void* d_out, int out_size)
{
    const float* start_state    = (const float*)d_in[0];
    const int*   instruction_id = (const int*)  d_in[1];
    const float* patterns       = (const float*)d_in[27];
    float*       out            = (float*)d_out;

    traj_kernel<<<B_ * CHUNKS_PER_B, TPB>>>(start_state, instruction_id, patterns, out);
}

// round 13
// speedup vs baseline: 1.0627x; 1.0295x over previous
#include <cuda_runtime.h>
#include <cstdint>

// out[b,t,a] = start_state[b,a] + (t/255) * patterns[iid[b], t, a]
// B=256, T=256, AD=64 -> each (b,t) row = 64 floats = 8 x 256-bit vectors.
//
// FINAL (= R9, best measured wall 8.64us): 1024 CTAs x 256 threads, each
// thread 2 front-batched 256-bit loads + 2 stores (LDG.E.256 / STG.E.256).
// Twelve structural variants (warp-LDG v4 MLP1/4/8, store hints, TMA load,
// 4-deep TMA pipeline, TMA store, cp.async, v8x4, v8x8, v8x4@TPB128) all
// land within a latency-bound + fixed-replay-overhead floor; this shape is
// the measured minimum.

#define B_   256
#define T_   256
#define AD_  64
#define TPB  256

struct f8 { float v[8]; };

__device__ __forceinline__ f8 ldg_v8(const float* p) {
    f8 r;
    asm volatile("ld.global.nc.v8.f32 {%0,%1,%2,%3,%4,%5,%6,%7}, [%8];"
                 : "=f"(r.v[0]), "=f"(r.v[1]), "=f"(r.v[2]), "=f"(r.v[3]),
                   "=f"(r.v[4]), "=f"(r.v[5]), "=f"(r.v[6]), "=f"(r.v[7])
                 : "l"(p));
    return r;
}

__device__ __forceinline__ void stg_v8(float* p, const f8& r) {
    asm volatile("st.global.v8.f32 [%0], {%1,%2,%3,%4,%5,%6,%7,%8};"
                 :: "l"(p),
                    "f"(r.v[0]), "f"(r.v[1]), "f"(r.v[2]), "f"(r.v[3]),
                    "f"(r.v[4]), "f"(r.v[5]), "f"(r.v[6]), "f"(r.v[7])
                 : "memory");
}

__global__ __launch_bounds__(TPB)
void traj_kernel(const float* __restrict__ start_state,    // [B, 64]
                 const int*   __restrict__ instruction_id, // [B]
                 const float* __restrict__ patterns,       // [V, T, 64]
                 float*       __restrict__ out)            // [B, T, 64]
{
    const unsigned bid   = blockIdx.x;
    const unsigned b     = bid >> 2;          // 4 chunks of 64 t per batch row
    const unsigned chunk = bid & 3u;
    const unsigned tid   = threadIdx.x;
    const unsigned a8    = tid & 7u;          // 256-bit slot within 64-float row
    const unsigned trow  = tid >> 3;          // 0..31
    const unsigned tbase = chunk * 64u;

    const int iid = __ldg(&instruction_id[b]);

    const f8 s = ldg_v8(start_state + (size_t)b * AD_ + a8 * 8u);

    const float* __restrict__ pat =
        patterns + ((size_t)iid * T_ + tbase) * AD_ + a8 * 8u;
    float* __restrict__ dst =
        out + ((size_t)b * T_ + tbase) * AD_ + a8 * 8u;

    // 2 independent 256-bit loads, front-batched.
    const unsigned t0 = trow;          // local t, iter 0
    const unsigned t1 = trow + 32u;    // local t, iter 1
    f8 p0 = ldg_v8(pat + (size_t)t0 * AD_);
    f8 p1 = ldg_v8(pat + (size_t)t1 * AD_);

    const float prog0 = (float)(tbase + t0) * (1.0f / (float)(T_ - 1));
    const float prog1 = (float)(tbase + t1) * (1.0f / (float)(T_ - 1));

    f8 r0, r1;
#pragma unroll
    for (int i = 0; i < 8; i++) r0.v[i] = fmaf(prog0, p0.v[i], s.v[i]);
#pragma unroll
    for (int i = 0; i < 8; i++) r1.v[i] = fmaf(prog1, p1.v[i], s.v[i]);

    stg_v8(dst + (size_t)t0 * AD_, r0);
    stg_v8(dst + (size_t)t1 * AD_, r1);
}

extern "C" void kernel_launch(void* const* d_in, const int* in_sizes, int n_in,
                              void* d_out, int out_size)
{
    const float* start_state    = (const float*)d_in[0];
    const int*   instruction_id = (const int*)  d_in[1];
    const float* patterns       = (const float*)d_in[27];
    float*       out            = (float*)d_out;

    traj_kernel<<<B_ * 4, TPB>>>(start_state, instruction_id, patterns, out);
}